// round 1
// baseline (speedup 1.0000x reference)
#include <cuda_runtime.h>

#define NN 100000
#define NE 1600000
#define SCAN_BS 1024
#define NBLK ((NN + SCAN_BS - 1) / SCAN_BS)   // 98

// ---------------- device scratch (no allocation allowed) ----------------
__device__ int    g_count[NN];
__device__ int    g_start[NN];
__device__ int    g_cursor[NN];
__device__ float  g_dis[NN];
__device__ int    g_bsum[NBLK];
__device__ int    g_boff[NBLK];
__device__ int    g_csr[NE];
__device__ float4 g_bufA[NN * 16];   // N x 64 floats
__device__ float4 g_bufB[NN * 16];   // N x 64 floats

// ---------------- CSR build ----------------
__global__ void __launch_bounds__(256) k_zero() {
    int i = blockIdx.x * 256 + threadIdx.x;
    if (i < NN) g_count[i] = 0;
}

__global__ void __launch_bounds__(256) k_hist(const int* __restrict__ dst) {
    int e = blockIdx.x * 256 + threadIdx.x;
    if (e < NE) atomicAdd(&g_count[dst[e]], 1);
}

__global__ void __launch_bounds__(256) k_dis() {
    int i = blockIdx.x * 256 + threadIdx.x;
    if (i < NN) g_dis[i] = rsqrtf((float)g_count[i] + 1.0f);
}

__global__ void __launch_bounds__(1024) k_bsum() {
    __shared__ int sh[1024];
    int t = threadIdx.x;
    int i = blockIdx.x * 1024 + t;
    sh[t] = (i < NN) ? g_count[i] : 0;
    __syncthreads();
    #pragma unroll
    for (int off = 512; off > 0; off >>= 1) {
        if (t < off) sh[t] += sh[t + off];
        __syncthreads();
    }
    if (t == 0) g_bsum[blockIdx.x] = sh[0];
}

__global__ void k_scanb() {
    __shared__ int sh[NBLK];
    int t = threadIdx.x;
    if (t < NBLK) sh[t] = g_bsum[t];
    __syncthreads();
    if (t == 0) {
        int run = 0;
        for (int b = 0; b < NBLK; b++) { g_boff[b] = run; run += sh[b]; }
    }
}

__global__ void __launch_bounds__(1024) k_scanfinal() {
    __shared__ int sh[1024];
    int t = threadIdx.x;
    int i = blockIdx.x * 1024 + t;
    int c = (i < NN) ? g_count[i] : 0;
    sh[t] = c;
    __syncthreads();
    #pragma unroll
    for (int off = 1; off < 1024; off <<= 1) {
        int v = (t >= off) ? sh[t - off] : 0;
        __syncthreads();
        sh[t] += v;
        __syncthreads();
    }
    if (i < NN) {
        int st = g_boff[blockIdx.x] + sh[t] - c;   // exclusive prefix
        g_start[i]  = st;
        g_cursor[i] = st;
    }
}

__global__ void __launch_bounds__(256) k_scatter(const int* __restrict__ src,
                                                 const int* __restrict__ dst) {
    int e = blockIdx.x * 256 + threadIdx.x;
    if (e < NE) {
        int d = dst[e];
        int p = atomicAdd(&g_cursor[d], 1);
        g_csr[p] = src[e];
    }
}

// ---------------- GEMM1: bufA = dis * (x @ W1), 128 -> 64 ----------------
__global__ void __launch_bounds__(256) k_gemm1(const float4* __restrict__ X,
                                               const float* __restrict__ W) {
    __shared__ __align__(16) float Wsh[128 * 64];
    __shared__ __align__(16) float xsh[8][128];
    int tid = threadIdx.x;
    // interleave (col j, col j+32) into adjacent floats for LDS.64
    for (int idx = tid; idx < 128 * 64; idx += 256) {
        int k = idx >> 6, c = idx & 63, j = c >> 1, h = c & 1;
        Wsh[idx] = W[k * 64 + j + (h << 5)];
    }
    __syncthreads();
    int warp = tid >> 5, lane = tid & 31;
    const float2* W2p = (const float2*)Wsh;
    float* out = (float*)g_bufA;
    for (int n = blockIdx.x * 8 + warp; n < NN; n += gridDim.x * 8) {
        ((float4*)xsh[warp])[lane] = X[n * 32 + lane];
        __syncwarp();
        float a0 = 0.f, a1 = 0.f;
        #pragma unroll
        for (int k = 0; k < 128; k++) {
            float  xk = xsh[warp][k];
            float2 wv = W2p[(k << 5) + lane];
            a0 = fmaf(xk, wv.x, a0);
            a1 = fmaf(xk, wv.y, a1);
        }
        float dn = g_dis[n];
        out[n * 64 + lane]      = dn * a0;
        out[n * 64 + 32 + lane] = dn * a1;
        __syncwarp();
    }
}

// ---------------- aggregation: out[d] = dis[d] * (sum_{s->d} in[s] + in[d]) ----------------
// RELU mode additionally applies: out = dis * relu(dis*acc + bias)  (conv1 epilogue fused)
// A2B: bufA -> bufB, else bufB -> bufA
template <bool RELU, bool A2B>
__global__ void __launch_bounds__(256) k_agg(const float* __restrict__ bias) {
    int warp = threadIdx.x >> 5, lane = threadIdx.x & 31;
    int n = blockIdx.x * 8 + warp;
    if (n >= NN) return;
    const float2* in  = A2B ? (const float2*)g_bufA : (const float2*)g_bufB;
    float2*       out = A2B ? (float2*)g_bufB       : (float2*)g_bufA;

    float2 acc = in[n * 32 + lane];          // self-loop term (already dis-scaled)
    int s0 = g_start[n], c = g_count[n];
    int e = 0;
    for (; e + 4 <= c; e += 4) {
        int i0 = g_csr[s0 + e],     i1 = g_csr[s0 + e + 1];
        int i2 = g_csr[s0 + e + 2], i3 = g_csr[s0 + e + 3];
        float2 v0 = in[i0 * 32 + lane], v1 = in[i1 * 32 + lane];
        float2 v2 = in[i2 * 32 + lane], v3 = in[i3 * 32 + lane];
        acc.x += (v0.x + v1.x) + (v2.x + v3.x);
        acc.y += (v0.y + v1.y) + (v2.y + v3.y);
    }
    for (; e < c; ++e) {
        int i = g_csr[s0 + e];
        float2 v = in[i * 32 + lane];
        acc.x += v.x; acc.y += v.y;
    }
    float dn = g_dis[n];
    float2 r;
    if (RELU) {
        float2 b = ((const float2*)bias)[lane];
        r.x = dn * fmaxf(fmaf(dn, acc.x, b.x), 0.f);
        r.y = dn * fmaxf(fmaf(dn, acc.y, b.y), 0.f);
    } else {
        r.x = dn * acc.x;
        r.y = dn * acc.y;
    }
    out[n * 32 + lane] = r;
}

// ---------------- GEMM2: bufB = dis * relu(bufA @ W2 + b2), 64 -> 64 ----------------
__global__ void __launch_bounds__(256) k_gemm2(const float* __restrict__ W,
                                               const float* __restrict__ b) {
    __shared__ __align__(16) float Wsh[64 * 64];
    __shared__ __align__(16) float xsh[8][64];
    int tid = threadIdx.x;
    for (int idx = tid; idx < 64 * 64; idx += 256) {
        int k = idx >> 6, c = idx & 63, j = c >> 1, h = c & 1;
        Wsh[idx] = W[k * 64 + j + (h << 5)];
    }
    __syncthreads();
    int warp = tid >> 5, lane = tid & 31;
    float blo = b[lane], bhi = b[lane + 32];
    const float2* W2p = (const float2*)Wsh;
    const float4* in  = (const float4*)g_bufA;
    float*        out = (float*)g_bufB;
    for (int n = blockIdx.x * 8 + warp; n < NN; n += gridDim.x * 8) {
        if (lane < 16) ((float4*)xsh[warp])[lane] = in[n * 16 + lane];
        __syncwarp();
        float a0 = 0.f, a1 = 0.f;
        #pragma unroll
        for (int k = 0; k < 64; k++) {
            float  xk = xsh[warp][k];
            float2 wv = W2p[(k << 5) + lane];
            a0 = fmaf(xk, wv.x, a0);
            a1 = fmaf(xk, wv.y, a1);
        }
        float dn = g_dis[n];
        out[n * 64 + lane]      = dn * fmaxf(a0 + blo, 0.f);
        out[n * 64 + 32 + lane] = dn * fmaxf(a1 + bhi, 0.f);
        __syncwarp();
    }
}

// ---------------- GEMM3: mu = bufA @ Wmu + bmu ; lv = bufA @ Wlv + blv ----------------
__global__ void __launch_bounds__(256) k_gemm3(const float* __restrict__ Wmu,
                                               const float* __restrict__ bmu,
                                               const float* __restrict__ Wlv,
                                               const float* __restrict__ blv,
                                               float* __restrict__ out) {
    __shared__ __align__(16) float Wsh[64 * 64];
    __shared__ __align__(16) float xsh[8][64];
    int tid = threadIdx.x;
    // interleave: even float = Wmu col j, odd float = Wlv col j
    for (int idx = tid; idx < 64 * 64; idx += 256) {
        int k = idx >> 6, c = idx & 63, j = c >> 1, h = c & 1;
        Wsh[idx] = h ? Wlv[k * 32 + j] : Wmu[k * 32 + j];
    }
    __syncthreads();
    int warp = tid >> 5, lane = tid & 31;
    float bm = bmu[lane], bl = blv[lane];
    const float2* W2p = (const float2*)Wsh;
    const float4* in  = (const float4*)g_bufA;
    for (int n = blockIdx.x * 8 + warp; n < NN; n += gridDim.x * 8) {
        if (lane < 16) ((float4*)xsh[warp])[lane] = in[n * 16 + lane];
        __syncwarp();
        float a0 = 0.f, a1 = 0.f;
        #pragma unroll
        for (int k = 0; k < 64; k++) {
            float  xk = xsh[warp][k];
            float2 wv = W2p[(k << 5) + lane];
            a0 = fmaf(xk, wv.x, a0);
            a1 = fmaf(xk, wv.y, a1);
        }
        out[n * 32 + lane]           = a0 + bm;   // mu
        out[NN * 32 + n * 32 + lane] = a1 + bl;   // logvar
        __syncwarp();
    }
}

// ---------------- launch ----------------
extern "C" void kernel_launch(void* const* d_in, const int* in_sizes, int n_in,
                              void* d_out, int out_size) {
    const float4* x   = (const float4*)d_in[0];
    const int*    ei  = (const int*)d_in[1];
    const float*  W1  = (const float*)d_in[2];
    const float*  b1  = (const float*)d_in[3];
    const float*  W2  = (const float*)d_in[4];
    const float*  b2  = (const float*)d_in[5];
    const float*  Wmu = (const float*)d_in[6];
    const float*  bmu = (const float*)d_in[7];
    const float*  Wlv = (const float*)d_in[8];
    const float*  blv = (const float*)d_in[9];
    float*        out = (float*)d_out;

    const int* src = ei;        // edge_index[0]
    const int* dst = ei + NE;   // edge_index[1]

    const int NB_N = (NN + 255) / 256;
    const int NB_E = (NE + 255) / 256;
    const int GEMM_GRID = 1184;          // 148 SMs * 8
    const int AGG_GRID  = (NN + 7) / 8;  // warp per node

    // CSR build (recomputed every call: deterministic, graph-capturable)
    k_zero<<<NB_N, 256>>>();
    k_hist<<<NB_E, 256>>>(dst);
    k_dis<<<NB_N, 256>>>();
    k_bsum<<<NBLK, 1024>>>();
    k_scanb<<<1, 128>>>();
    k_scanfinal<<<NBLK, 1024>>>();
    k_scatter<<<NB_E, 256>>>(src, dst);

    // Layer pipeline (agg commutes with linear transforms)
    k_gemm1<<<GEMM_GRID, 256>>>(x, W1);                 // bufA = dis*(x@W1)
    k_agg<true,  true ><<<AGG_GRID, 256>>>(b1);         // bufB = dis*relu(dis*S(bufA)+b1)
    k_agg<false, false><<<AGG_GRID, 256>>>(nullptr);    // bufA = dis*S(bufB)
    k_gemm2<<<GEMM_GRID, 256>>>(W2, b2);                // bufB = dis*relu(bufA@W2+b2)
    k_agg<false, false><<<AGG_GRID, 256>>>(nullptr);    // bufA = dis*S(bufB)
    k_gemm3<<<GEMM_GRID, 256>>>(Wmu, bmu, Wlv, blv, out); // out = {mu, logvar}
}

// round 2
// speedup vs baseline: 1.4677x; 1.4677x over previous
#include <cuda_runtime.h>

#define NN 100000
#define NE 1600000
#define SCAN_BS 1024
#define NBLK ((NN + SCAN_BS - 1) / SCAN_BS)   // 98

// packed fp32x2 FMA: d = a*b + d (elementwise on two packed floats)
#define FFMA2(d, a, b) \
    asm("fma.rn.f32x2 %0, %1, %2, %0;" : "+l"(d) : "l"(a), "l"(b))

__device__ __forceinline__ float f2sum(unsigned long long v) {
    float lo = __uint_as_float((unsigned)(v & 0xffffffffu));
    float hi = __uint_as_float((unsigned)(v >> 32));
    return lo + hi;
}

// ---------------- device scratch (no allocation allowed) ----------------
__device__ int    g_count[NN];
__device__ int    g_start[NN];
__device__ int    g_cursor[NN];
__device__ float  g_dis[NN];
__device__ int    g_bsum[NBLK];
__device__ int    g_boff[NBLK];
__device__ int    g_csr[NE];
__device__ float4 g_bufA[NN * 16];   // N x 64 floats
__device__ float4 g_bufB[NN * 16];   // N x 64 floats

// ---------------- CSR build ----------------
__global__ void __launch_bounds__(256) k_zero() {
    int i = blockIdx.x * 256 + threadIdx.x;
    if (i < NN) g_count[i] = 0;
}

__global__ void __launch_bounds__(256) k_hist(const int* __restrict__ dst) {
    int e = blockIdx.x * 256 + threadIdx.x;
    if (e < NE) atomicAdd(&g_count[dst[e]], 1);
}

__global__ void __launch_bounds__(256) k_dis() {
    int i = blockIdx.x * 256 + threadIdx.x;
    if (i < NN) g_dis[i] = rsqrtf((float)g_count[i] + 1.0f);
}

__global__ void __launch_bounds__(1024) k_bsum() {
    __shared__ int sh[1024];
    int t = threadIdx.x;
    int i = blockIdx.x * 1024 + t;
    sh[t] = (i < NN) ? g_count[i] : 0;
    __syncthreads();
    #pragma unroll
    for (int off = 512; off > 0; off >>= 1) {
        if (t < off) sh[t] += sh[t + off];
        __syncthreads();
    }
    if (t == 0) g_bsum[blockIdx.x] = sh[0];
}

__global__ void k_scanb() {
    __shared__ int sh[NBLK];
    int t = threadIdx.x;
    if (t < NBLK) sh[t] = g_bsum[t];
    __syncthreads();
    if (t == 0) {
        int run = 0;
        for (int b = 0; b < NBLK; b++) { g_boff[b] = run; run += sh[b]; }
    }
}

__global__ void __launch_bounds__(1024) k_scanfinal() {
    __shared__ int sh[1024];
    int t = threadIdx.x;
    int i = blockIdx.x * 1024 + t;
    int c = (i < NN) ? g_count[i] : 0;
    sh[t] = c;
    __syncthreads();
    #pragma unroll
    for (int off = 1; off < 1024; off <<= 1) {
        int v = (t >= off) ? sh[t - off] : 0;
        __syncthreads();
        sh[t] += v;
        __syncthreads();
    }
    if (i < NN) {
        int st = g_boff[blockIdx.x] + sh[t] - c;   // exclusive prefix
        g_start[i]  = st;
        g_cursor[i] = st;
    }
}

__global__ void __launch_bounds__(256) k_scatter(const int* __restrict__ src,
                                                 const int* __restrict__ dst) {
    int e = blockIdx.x * 256 + threadIdx.x;
    if (e < NE) {
        int d = dst[e];
        int p = atomicAdd(&g_cursor[d], 1);
        g_csr[p] = src[e];
    }
}

// ---------------- GEMM1: bufA = dis * (x @ W1), 128 -> 64 ----------------
// W staged transposed in k-quads: Wq[c][j] = {W[4c][j],W[4c+1][j],W[4c+2][j],W[4c+3][j]}
// 4 rows per warp; accumulators are packed f32x2 over (even-k, odd-k) partial sums.
__global__ void __launch_bounds__(256) k_gemm1(const float4* __restrict__ X,
                                               const float* __restrict__ W) {
    __shared__ __align__(16) float4 Wq[32 * 64];   // 32KB
    __shared__ __align__(16) float4 xq[8][4 * 32]; // 16KB: per warp, 4 rows x 32 f4
    int tid = threadIdx.x;
    float* Wf = (float*)Wq;
    for (int idx = tid; idx < 128 * 64; idx += 256) {
        int c = idx >> 8;            // k-quad
        int j = (idx >> 2) & 63;     // column
        int r = idx & 3;             // k within quad
        Wf[idx] = W[(c * 4 + r) * 64 + j];
    }
    __syncthreads();
    int warp = tid >> 5, lane = tid & 31;
    const ulonglong2* Wu = (const ulonglong2*)Wq;
    const ulonglong2* xu = (const ulonglong2*)xq[warp];
    float* out = (float*)g_bufA;
    for (int t = blockIdx.x * 8 + warp; t < NN / 4; t += gridDim.x * 8) {
        int n0 = t * 4;
        #pragma unroll
        for (int r = 0; r < 4; r++)
            xq[warp][r * 32 + lane] = X[(n0 + r) * 32 + lane];
        __syncwarp();
        unsigned long long aL[4] = {0,0,0,0}, aH[4] = {0,0,0,0};
        #pragma unroll
        for (int c = 0; c < 32; c++) {
            ulonglong2 w0 = Wu[c * 64 + lane];
            ulonglong2 w1 = Wu[c * 64 + lane + 32];
            #pragma unroll
            for (int r = 0; r < 4; r++) {
                ulonglong2 xv = xu[r * 32 + c];
                FFMA2(aL[r], xv.x, w0.x);
                FFMA2(aL[r], xv.y, w0.y);
                FFMA2(aH[r], xv.x, w1.x);
                FFMA2(aH[r], xv.y, w1.y);
            }
        }
        #pragma unroll
        for (int r = 0; r < 4; r++) {
            int n = n0 + r;
            float dn = g_dis[n];
            out[n * 64 + lane]      = dn * f2sum(aL[r]);
            out[n * 64 + 32 + lane] = dn * f2sum(aH[r]);
        }
        __syncwarp();
    }
}

// ---------------- aggregation: out[d] = dis[d] * (sum_{s->d} in[s] + in[d]) ----------------
template <bool RELU, bool A2B>
__global__ void __launch_bounds__(256) k_agg(const float* __restrict__ bias) {
    int warp = threadIdx.x >> 5, lane = threadIdx.x & 31;
    int n = blockIdx.x * 8 + warp;
    if (n >= NN) return;
    const float2* in  = A2B ? (const float2*)g_bufA : (const float2*)g_bufB;
    float2*       out = A2B ? (float2*)g_bufB       : (float2*)g_bufA;

    float2 acc = in[n * 32 + lane];          // self-loop term (already dis-scaled)
    int s0 = g_start[n], c = g_count[n];
    int e = 0;
    for (; e + 4 <= c; e += 4) {
        int i0 = g_csr[s0 + e],     i1 = g_csr[s0 + e + 1];
        int i2 = g_csr[s0 + e + 2], i3 = g_csr[s0 + e + 3];
        float2 v0 = in[i0 * 32 + lane], v1 = in[i1 * 32 + lane];
        float2 v2 = in[i2 * 32 + lane], v3 = in[i3 * 32 + lane];
        acc.x += (v0.x + v1.x) + (v2.x + v3.x);
        acc.y += (v0.y + v1.y) + (v2.y + v3.y);
    }
    for (; e < c; ++e) {
        int i = g_csr[s0 + e];
        float2 v = in[i * 32 + lane];
        acc.x += v.x; acc.y += v.y;
    }
    float dn = g_dis[n];
    float2 r;
    if (RELU) {
        float2 b = ((const float2*)bias)[lane];
        r.x = dn * fmaxf(fmaf(dn, acc.x, b.x), 0.f);
        r.y = dn * fmaxf(fmaf(dn, acc.y, b.y), 0.f);
    } else {
        r.x = dn * acc.x;
        r.y = dn * acc.y;
    }
    out[n * 32 + lane] = r;
}

// ---------------- GEMM2: bufB = dis * relu(bufA @ W2 + b2), 64 -> 64 ----------------
__global__ void __launch_bounds__(256) k_gemm2(const float* __restrict__ W,
                                               const float* __restrict__ b) {
    __shared__ __align__(16) float4 Wq[16 * 64];   // 16KB
    __shared__ __align__(16) float4 xq[8][4 * 16]; // 8KB
    int tid = threadIdx.x;
    float* Wf = (float*)Wq;
    for (int idx = tid; idx < 64 * 64; idx += 256) {
        int c = idx >> 8;
        int j = (idx >> 2) & 63;
        int r = idx & 3;
        Wf[idx] = W[(c * 4 + r) * 64 + j];
    }
    __syncthreads();
    int warp = tid >> 5, lane = tid & 31;
    float blo = b[lane], bhi = b[lane + 32];
    const ulonglong2* Wu = (const ulonglong2*)Wq;
    const ulonglong2* xu = (const ulonglong2*)xq[warp];
    const float4* in  = (const float4*)g_bufA;
    float*        out = (float*)g_bufB;
    int half = lane >> 4, sub = lane & 15;
    for (int t = blockIdx.x * 8 + warp; t < NN / 4; t += gridDim.x * 8) {
        int n0 = t * 4;
        #pragma unroll
        for (int h = 0; h < 2; h++) {
            int r = h * 2 + half;
            xq[warp][r * 16 + sub] = in[(n0 + r) * 16 + sub];
        }
        __syncwarp();
        unsigned long long aL[4] = {0,0,0,0}, aH[4] = {0,0,0,0};
        #pragma unroll
        for (int c = 0; c < 16; c++) {
            ulonglong2 w0 = Wu[c * 64 + lane];
            ulonglong2 w1 = Wu[c * 64 + lane + 32];
            #pragma unroll
            for (int r = 0; r < 4; r++) {
                ulonglong2 xv = xu[r * 16 + c];
                FFMA2(aL[r], xv.x, w0.x);
                FFMA2(aL[r], xv.y, w0.y);
                FFMA2(aH[r], xv.x, w1.x);
                FFMA2(aH[r], xv.y, w1.y);
            }
        }
        #pragma unroll
        for (int r = 0; r < 4; r++) {
            int n = n0 + r;
            float dn = g_dis[n];
            out[n * 64 + lane]      = dn * fmaxf(f2sum(aL[r]) + blo, 0.f);
            out[n * 64 + 32 + lane] = dn * fmaxf(f2sum(aH[r]) + bhi, 0.f);
        }
        __syncwarp();
    }
}

// ---------------- GEMM3: mu = bufA @ Wmu + bmu ; lv = bufA @ Wlv + blv ----------------
__global__ void __launch_bounds__(256) k_gemm3(const float* __restrict__ Wmu,
                                               const float* __restrict__ bmu,
                                               const float* __restrict__ Wlv,
                                               const float* __restrict__ blv,
                                               float* __restrict__ out) {
    __shared__ __align__(16) float4 Wq[16 * 64];   // 16KB  (cols 0..31 = Wmu, 32..63 = Wlv)
    __shared__ __align__(16) float4 xq[8][4 * 16]; // 8KB
    int tid = threadIdx.x;
    float* Wf = (float*)Wq;
    for (int idx = tid; idx < 64 * 64; idx += 256) {
        int c = idx >> 8;
        int j = (idx >> 2) & 63;
        int r = idx & 3;
        int k = c * 4 + r;
        Wf[idx] = (j < 32) ? Wmu[k * 32 + j] : Wlv[k * 32 + (j - 32)];
    }
    __syncthreads();
    int warp = tid >> 5, lane = tid & 31;
    float bm = bmu[lane], bl = blv[lane];
    const ulonglong2* Wu = (const ulonglong2*)Wq;
    const ulonglong2* xu = (const ulonglong2*)xq[warp];
    const float4* in = (const float4*)g_bufA;
    int half = lane >> 4, sub = lane & 15;
    for (int t = blockIdx.x * 8 + warp; t < NN / 4; t += gridDim.x * 8) {
        int n0 = t * 4;
        #pragma unroll
        for (int h = 0; h < 2; h++) {
            int r = h * 2 + half;
            xq[warp][r * 16 + sub] = in[(n0 + r) * 16 + sub];
        }
        __syncwarp();
        unsigned long long aL[4] = {0,0,0,0}, aH[4] = {0,0,0,0};
        #pragma unroll
        for (int c = 0; c < 16; c++) {
            ulonglong2 w0 = Wu[c * 64 + lane];        // Wmu col lane
            ulonglong2 w1 = Wu[c * 64 + lane + 32];   // Wlv col lane
            #pragma unroll
            for (int r = 0; r < 4; r++) {
                ulonglong2 xv = xu[r * 16 + c];
                FFMA2(aL[r], xv.x, w0.x);
                FFMA2(aL[r], xv.y, w0.y);
                FFMA2(aH[r], xv.x, w1.x);
                FFMA2(aH[r], xv.y, w1.y);
            }
        }
        #pragma unroll
        for (int r = 0; r < 4; r++) {
            int n = n0 + r;
            out[n * 32 + lane]           = f2sum(aL[r]) + bm;   // mu
            out[NN * 32 + n * 32 + lane] = f2sum(aH[r]) + bl;   // logvar
        }
        __syncwarp();
    }
}

// ---------------- launch ----------------
extern "C" void kernel_launch(void* const* d_in, const int* in_sizes, int n_in,
                              void* d_out, int out_size) {
    const float4* x   = (const float4*)d_in[0];
    const int*    ei  = (const int*)d_in[1];
    const float*  W1  = (const float*)d_in[2];
    const float*  b1  = (const float*)d_in[3];
    const float*  W2  = (const float*)d_in[4];
    const float*  b2  = (const float*)d_in[5];
    const float*  Wmu = (const float*)d_in[6];
    const float*  bmu = (const float*)d_in[7];
    const float*  Wlv = (const float*)d_in[8];
    const float*  blv = (const float*)d_in[9];
    float*        out = (float*)d_out;

    const int* src = ei;        // edge_index[0]
    const int* dst = ei + NE;   // edge_index[1]

    const int NB_N = (NN + 255) / 256;
    const int NB_E = (NE + 255) / 256;
    const int GEMM_GRID = 1184;          // 148 SMs * 8
    const int AGG_GRID  = (NN + 7) / 8;  // warp per node

    // CSR build (recomputed every call: deterministic, graph-capturable)
    k_zero<<<NB_N, 256>>>();
    k_hist<<<NB_E, 256>>>(dst);
    k_dis<<<NB_N, 256>>>();
    k_bsum<<<NBLK, 1024>>>();
    k_scanb<<<1, 128>>>();
    k_scanfinal<<<NBLK, 1024>>>();
    k_scatter<<<NB_E, 256>>>(src, dst);

    // Layer pipeline (agg commutes with linear transforms)
    k_gemm1<<<GEMM_GRID, 256>>>(x, W1);                 // bufA = dis*(x@W1)
    k_agg<true,  true ><<<AGG_GRID, 256>>>(b1);         // bufB = dis*relu(dis*S(bufA)+b1)
    k_agg<false, false><<<AGG_GRID, 256>>>(nullptr);    // bufA = dis*S(bufB)
    k_gemm2<<<GEMM_GRID, 256>>>(W2, b2);                // bufB = dis*relu(bufA@W2+b2)
    k_agg<false, false><<<AGG_GRID, 256>>>(nullptr);    // bufA = dis*S(bufB)
    k_gemm3<<<GEMM_GRID, 256>>>(Wmu, bmu, Wlv, blv, out); // out = {mu, logvar}
}

// round 6
// speedup vs baseline: 1.5225x; 1.0373x over previous
#include <cuda_runtime.h>
#include <cuda_fp16.h>

#define NN 100000
#define NE 1600000
#define SCAN_BS 1024
#define NBLK ((NN + SCAN_BS - 1) / SCAN_BS)   // 98

// packed fp32x2 FMA: d = a*b + d (elementwise on two packed floats)
#define FFMA2(d, a, b) \
    asm("fma.rn.f32x2 %0, %1, %2, %0;" : "+l"(d) : "l"(a), "l"(b))

__device__ __forceinline__ float f2sum(unsigned long long v) {
    float lo = __uint_as_float((unsigned)(v & 0xffffffffu));
    float hi = __uint_as_float((unsigned)(v >> 32));
    return lo + hi;
}

// ---------------- device scratch (no allocation allowed) ----------------
__device__ int    g_count[NN];
__device__ int    g_start[NN];
__device__ int    g_cursor[NN];
__device__ float  g_dis[NN];
__device__ unsigned long long g_aggp[NBLK];   // scan: bit32 = valid, low 32 = block aggregate
__device__ int    g_csr[NE];
__device__ __half2 g_hA[NN * 32];   // N x 64 half (gemm1 out / agg1 in)
__device__ __half2 g_hB[NN * 32];   // N x 64 half (agg1 out / gemm2 out)
__device__ float4  g_fA[NN * 16];   // N x 64 float (agg2/agg3 out, gemm2/3 in)

// ---------------- CSR build ----------------
__global__ void __launch_bounds__(256) k_zero() {
    int i = blockIdx.x * 256 + threadIdx.x;
    if (i < NN) g_count[i] = 0;
    if (i < NBLK) g_aggp[i] = 0ull;
}

__global__ void __launch_bounds__(256) k_hist(const int* __restrict__ dst) {
    int e = blockIdx.x * 256 + threadIdx.x;
    if (e < NE) atomicAdd(&g_count[dst[e]], 1);
}

// single-pass scan with decoupled lookback; also computes dis & cursor
__global__ void __launch_bounds__(1024) k_scan() {
    __shared__ int wsum[32];
    __shared__ int s_red[32];
    int t = threadIdx.x, b = blockIdx.x;
    int lane = t & 31, warp = t >> 5;
    int i = b * SCAN_BS + t;
    int c = (i < NN) ? g_count[i] : 0;

    // warp inclusive scan
    int v = c;
    #pragma unroll
    for (int off = 1; off < 32; off <<= 1) {
        int u = __shfl_up_sync(0xffffffffu, v, off);
        if (lane >= off) v += u;
    }
    if (lane == 31) wsum[warp] = v;
    __syncthreads();
    if (warp == 0) {
        int w = wsum[lane];
        #pragma unroll
        for (int off = 1; off < 32; off <<= 1) {
            int u = __shfl_up_sync(0xffffffffu, w, off);
            if (lane >= off) w += u;
        }
        wsum[lane] = w;
    }
    __syncthreads();
    int incl = v + (warp ? wsum[warp - 1] : 0);
    int total = wsum[31];

    // publish this block's aggregate
    if (t == 0) atomicExch(&g_aggp[b], 0x100000000ull | (unsigned)total);

    // lookback: prefix = sum of aggregates of blocks < b (b <= 97, parallel spin)
    int pf = 0;
    if (t < b) {
        unsigned long long a;
        do { a = atomicAdd(&g_aggp[t], 0ull); } while (!(a >> 32));
        pf = (int)(unsigned)a;
    }
    #pragma unroll
    for (int off = 16; off > 0; off >>= 1)
        pf += __shfl_xor_sync(0xffffffffu, pf, off);
    if (lane == 0) s_red[warp] = pf;
    __syncthreads();
    if (warp == 0) {
        int r = s_red[lane];
        #pragma unroll
        for (int off = 16; off > 0; off >>= 1)
            r += __shfl_xor_sync(0xffffffffu, r, off);
        if (lane == 0) s_red[0] = r;
    }
    __syncthreads();
    int prefix = s_red[0];

    if (i < NN) {
        int st = prefix + incl - c;   // exclusive
        g_start[i]  = st;
        g_cursor[i] = st;
        g_dis[i]    = rsqrtf((float)c + 1.0f);
    }
}

__global__ void __launch_bounds__(256) k_scatter(const int* __restrict__ src,
                                                 const int* __restrict__ dst) {
    int e = blockIdx.x * 256 + threadIdx.x;
    if (e < NE) {
        int d = dst[e];
        int p = atomicAdd(&g_cursor[d], 1);
        g_csr[p] = src[e];
    }
}

// ---------------- GEMM1: hA = fp16(dis * (x @ W1)), 128 -> 64 ----------------
__global__ void __launch_bounds__(256) k_gemm1(const float4* __restrict__ X,
                                               const float* __restrict__ W) {
    __shared__ __align__(16) float4 Wq[32 * 64];   // 32KB, k-quad staged
    __shared__ __align__(16) float4 xq[8][4 * 32]; // 16KB
    int tid = threadIdx.x;
    float* Wf = (float*)Wq;
    for (int idx = tid; idx < 128 * 64; idx += 256) {
        int c = idx >> 8;            // k-quad
        int j = (idx >> 2) & 63;     // column
        int r = idx & 3;             // k within quad
        Wf[idx] = W[(c * 4 + r) * 64 + j];
    }
    __syncthreads();
    int warp = tid >> 5, lane = tid & 31;
    const ulonglong2* Wu = (const ulonglong2*)Wq;
    const ulonglong2* xu = (const ulonglong2*)xq[warp];
    __half* out = (__half*)g_hA;
    for (int t = blockIdx.x * 8 + warp; t < NN / 4; t += gridDim.x * 8) {
        int n0 = t * 4;
        #pragma unroll
        for (int r = 0; r < 4; r++)
            xq[warp][r * 32 + lane] = X[(n0 + r) * 32 + lane];
        __syncwarp();
        unsigned long long aL[4] = {0,0,0,0}, aH[4] = {0,0,0,0};
        #pragma unroll
        for (int c = 0; c < 32; c++) {
            ulonglong2 w0 = Wu[c * 64 + lane];
            ulonglong2 w1 = Wu[c * 64 + lane + 32];
            #pragma unroll
            for (int r = 0; r < 4; r++) {
                ulonglong2 xv = xu[r * 32 + c];
                FFMA2(aL[r], xv.x, w0.x);
                FFMA2(aL[r], xv.y, w0.y);
                FFMA2(aH[r], xv.x, w1.x);
                FFMA2(aH[r], xv.y, w1.y);
            }
        }
        #pragma unroll
        for (int r = 0; r < 4; r++) {
            int n = n0 + r;
            float dn = g_dis[n];
            out[n * 64 + lane]      = __float2half(dn * f2sum(aL[r]));
            out[n * 64 + 32 + lane] = __float2half(dn * f2sum(aH[r]));
        }
        __syncwarp();
    }
}

// ---------------- aggregation: out[d] = dis[d]*(sum_{s->d} in[s] + in[d]) ----------------
// fp16 input, fp32 accumulate. RELU: out = dis*relu(dis*acc + bias).
// IN_A: read hA else hB.  OUT_HALF: write hB (fp16) else fA (fp32).
template <bool RELU, bool IN_A, bool OUT_HALF>
__global__ void __launch_bounds__(256) k_agg(const float* __restrict__ bias) {
    int warp = threadIdx.x >> 5, lane = threadIdx.x & 31;
    int n = blockIdx.x * 8 + warp;
    if (n >= NN) return;
    const __half2* in = IN_A ? (const __half2*)g_hA : (const __half2*)g_hB;

    float2 acc = __half22float2(in[n * 32 + lane]);   // self-loop (already dis-scaled)
    int s0 = g_start[n], c = g_count[n];
    int e = 0;
    for (; e + 4 <= c; e += 4) {
        int i0 = g_csr[s0 + e],     i1 = g_csr[s0 + e + 1];
        int i2 = g_csr[s0 + e + 2], i3 = g_csr[s0 + e + 3];
        float2 v0 = __half22float2(in[i0 * 32 + lane]);
        float2 v1 = __half22float2(in[i1 * 32 + lane]);
        float2 v2 = __half22float2(in[i2 * 32 + lane]);
        float2 v3 = __half22float2(in[i3 * 32 + lane]);
        acc.x += (v0.x + v1.x) + (v2.x + v3.x);
        acc.y += (v0.y + v1.y) + (v2.y + v3.y);
    }
    for (; e < c; ++e) {
        float2 v = __half22float2(in[g_csr[s0 + e] * 32 + lane]);
        acc.x += v.x; acc.y += v.y;
    }
    float dn = g_dis[n];
    float2 r;
    if (RELU) {
        float2 b = ((const float2*)bias)[lane];
        r.x = dn * fmaxf(fmaf(dn, acc.x, b.x), 0.f);
        r.y = dn * fmaxf(fmaf(dn, acc.y, b.y), 0.f);
    } else {
        r.x = dn * acc.x;
        r.y = dn * acc.y;
    }
    if (OUT_HALF) {
        ((__half2*)g_hB)[n * 32 + lane] = __float22half2_rn(r);
    } else {
        ((float2*)g_fA)[n * 32 + lane] = r;
    }
}

// ---------------- GEMM2: hB = fp16(dis * relu(fA @ W2 + b2)), 64 -> 64 ----------------
__global__ void __launch_bounds__(256) k_gemm2(const float* __restrict__ W,
                                               const float* __restrict__ b) {
    __shared__ __align__(16) float4 Wq[16 * 64];   // 16KB
    __shared__ __align__(16) float4 xq[8][4 * 16]; // 8KB
    int tid = threadIdx.x;
    float* Wf = (float*)Wq;
    for (int idx = tid; idx < 64 * 64; idx += 256) {
        int c = idx >> 8;
        int j = (idx >> 2) & 63;
        int r = idx & 3;
        Wf[idx] = W[(c * 4 + r) * 64 + j];
    }
    __syncthreads();
    int warp = tid >> 5, lane = tid & 31;
    float blo = b[lane], bhi = b[lane + 32];
    const ulonglong2* Wu = (const ulonglong2*)Wq;
    const ulonglong2* xu = (const ulonglong2*)xq[warp];
    const float4* in = (const float4*)g_fA;
    __half* out = (__half*)g_hB;
    int half_ = lane >> 4, sub = lane & 15;
    for (int t = blockIdx.x * 8 + warp; t < NN / 4; t += gridDim.x * 8) {
        int n0 = t * 4;
        #pragma unroll
        for (int h = 0; h < 2; h++) {
            int r = h * 2 + half_;
            xq[warp][r * 16 + sub] = in[(n0 + r) * 16 + sub];
        }
        __syncwarp();
        unsigned long long aL[4] = {0,0,0,0}, aH[4] = {0,0,0,0};
        #pragma unroll
        for (int c = 0; c < 16; c++) {
            ulonglong2 w0 = Wu[c * 64 + lane];
            ulonglong2 w1 = Wu[c * 64 + lane + 32];
            #pragma unroll
            for (int r = 0; r < 4; r++) {
                ulonglong2 xv = xu[r * 16 + c];
                FFMA2(aL[r], xv.x, w0.x);
                FFMA2(aL[r], xv.y, w0.y);
                FFMA2(aH[r], xv.x, w1.x);
                FFMA2(aH[r], xv.y, w1.y);
            }
        }
        #pragma unroll
        for (int r = 0; r < 4; r++) {
            int n = n0 + r;
            float dn = g_dis[n];
            out[n * 64 + lane]      = __float2half(dn * fmaxf(f2sum(aL[r]) + blo, 0.f));
            out[n * 64 + 32 + lane] = __float2half(dn * fmaxf(f2sum(aH[r]) + bhi, 0.f));
        }
        __syncwarp();
    }
}

// ---------------- GEMM3: mu = fA @ Wmu + bmu ; lv = fA @ Wlv + blv ----------------
__global__ void __launch_bounds__(256) k_gemm3(const float* __restrict__ Wmu,
                                               const float* __restrict__ bmu,
                                               const float* __restrict__ Wlv,
                                               const float* __restrict__ blv,
                                               float* __restrict__ out) {
    __shared__ __align__(16) float4 Wq[16 * 64];   // cols 0..31 = Wmu, 32..63 = Wlv
    __shared__ __align__(16) float4 xq[8][4 * 16];
    int tid = threadIdx.x;
    float* Wf = (float*)Wq;
    for (int idx = tid; idx < 64 * 64; idx += 256) {
        int c = idx >> 8;
        int j = (idx >> 2) & 63;
        int r = idx & 3;
        int k = c * 4 + r;
        Wf[idx] = (j < 32) ? Wmu[k * 32 + j] : Wlv[k * 32 + (j - 32)];
    }
    __syncthreads();
    int warp = tid >> 5, lane = tid & 31;
    float bm = bmu[lane], bl = blv[lane];
    const ulonglong2* Wu = (const ulonglong2*)Wq;
    const ulonglong2* xu = (const ulonglong2*)xq[warp];
    const float4* in = (const float4*)g_fA;
    int half_ = lane >> 4, sub = lane & 15;
    for (int t = blockIdx.x * 8 + warp; t < NN / 4; t += gridDim.x * 8) {
        int n0 = t * 4;
        #pragma unroll
        for (int h = 0; h < 2; h++) {
            int r = h * 2 + half_;
            xq[warp][r * 16 + sub] = in[(n0 + r) * 16 + sub];
        }
        __syncwarp();
        unsigned long long aL[4] = {0,0,0,0}, aH[4] = {0,0,0,0};
        #pragma unroll
        for (int c = 0; c < 16; c++) {
            ulonglong2 w0 = Wu[c * 64 + lane];        // Wmu col lane
            ulonglong2 w1 = Wu[c * 64 + lane + 32];   // Wlv col lane
            #pragma unroll
            for (int r = 0; r < 4; r++) {
                ulonglong2 xv = xu[r * 16 + c];
                FFMA2(aL[r], xv.x, w0.x);
                FFMA2(aL[r], xv.y, w0.y);
                FFMA2(aH[r], xv.x, w1.x);
                FFMA2(aH[r], xv.y, w1.y);
            }
        }
        #pragma unroll
        for (int r = 0; r < 4; r++) {
            int n = n0 + r;
            out[n * 32 + lane]           = f2sum(aL[r]) + bm;   // mu
            out[NN * 32 + n * 32 + lane] = f2sum(aH[r]) + bl;   // logvar
        }
        __syncwarp();
    }
}

// ---------------- launch ----------------
extern "C" void kernel_launch(void* const* d_in, const int* in_sizes, int n_in,
                              void* d_out, int out_size) {
    const float4* x   = (const float4*)d_in[0];
    const int*    ei  = (const int*)d_in[1];
    const float*  W1  = (const float*)d_in[2];
    const float*  b1  = (const float*)d_in[3];
    const float*  W2  = (const float*)d_in[4];
    const float*  b2  = (const float*)d_in[5];
    const float*  Wmu = (const float*)d_in[6];
    const float*  bmu = (const float*)d_in[7];
    const float*  Wlv = (const float*)d_in[8];
    const float*  blv = (const float*)d_in[9];
    float*        out = (float*)d_out;

    const int* src = ei;        // edge_index[0]
    const int* dst = ei + NE;   // edge_index[1]

    const int NB_N = (NN + 255) / 256;
    const int NB_E = (NE + 255) / 256;
    const int GEMM_GRID = 1184;          // 148 SMs * 8
    const int AGG_GRID  = (NN + 7) / 8;  // warp per node

    // CSR build (4 launches)
    k_zero<<<NB_N, 256>>>();
    k_hist<<<NB_E, 256>>>(dst);
    k_scan<<<NBLK, SCAN_BS>>>();
    k_scatter<<<NB_E, 256>>>(src, dst);

    // Layer pipeline (agg commutes with linear transforms)
    k_gemm1<<<GEMM_GRID, 256>>>(x, W1);                       // hA = fp16(dis*(x@W1))
    k_agg<true,  true,  true ><<<AGG_GRID, 256>>>(b1);        // hB = fp16(dis*relu(dis*S(hA)+b1))
    k_agg<false, false, false><<<AGG_GRID, 256>>>(nullptr);   // fA = dis*S(hB)
    k_gemm2<<<GEMM_GRID, 256>>>(W2, b2);                      // hB = fp16(dis*relu(fA@W2+b2))
    k_agg<false, false, false><<<AGG_GRID, 256>>>(nullptr);   // fA = dis*S(hB)
    k_gemm3<<<GEMM_GRID, 256>>>(Wmu, bmu, Wlv, blv, out);     // out = {mu, logvar}
}